// round 2
// baseline (speedup 1.0000x reference)
#include <cuda_runtime.h>
#include <math.h>

#define N_RES  20000
#define N_EDGE 640000
#define FDIM   340
#define NUM_AA 21

// ---------------- device scratch (no allocations allowed) ----------------
__device__ int            g_mask_mode;          // 0=f32, 1=i32, 2=u8
__device__ unsigned char  g_mask[N_RES];
__device__ float          g_nodeA[N_RES * 24];  // [0:12) bb (N,CA,C,CB), [12:24) local = R^T(bb - t)
__device__ float          g_nodeB[N_RES * 12];  // [0:9) R row-major R[j*3+i], [9:12) t
__device__ float          g_freq[8];            // positional frequencies (match XLA f32 exp)

// ---------------- detect noising_mask dtype + compute freqs ----------------
__global__ void detect_kernel(const unsigned int* __restrict__ m) {
    bool isFloat = false, isByte = false;
    #pragma unroll 1
    for (int i = 0; i < 64; ++i) {
        unsigned w = m[i];
        if (w == 0x3F800000u)          isFloat = true;
        else if (w != 0u && w != 1u)   isByte  = true;
    }
    g_mask_mode = isByte ? 2 : (isFloat ? 0 : 1);

    // freq[k] = exp(float(2k) * float(-ln(10000)/16)), rounded like XLA f32 exp
    const float basef = -0.5756462732485115f;
    for (int k = 0; k < 8; ++k) {
        float arg = (float)(2 * k) * basef;       // exact-order match to reference
        g_freq[k] = (float)exp((double)arg);      // correctly-rounded f32 result
    }
}

__global__ void convert_mask_kernel(const void* __restrict__ m) {
    int r = blockIdx.x * blockDim.x + threadIdx.x;
    if (r >= N_RES) return;
    int mode = g_mask_mode;
    unsigned char v;
    if (mode == 2)       v = (((const unsigned char*)m)[r] != 0);
    else if (mode == 1)  v = (((const int*)m)[r] != 0);
    else                 v = (((const float*)m)[r] != 0.0f);
    g_mask[r] = v;
}

// ---------------- per-residue precompute ----------------
__global__ void node_kernel(const float* __restrict__ atom14,
                            const float* __restrict__ rig) {
    int r = blockIdx.x * blockDim.x + threadIdx.x;
    if (r >= N_RES) return;

    const float* a = atom14 + (size_t)r * 14 * 3;
    float n0 = a[0], n1 = a[1], n2 = a[2];
    float ca0 = a[3], ca1 = a[4], ca2 = a[5];
    float c0 = a[6], c1 = a[7], c2 = a[8];

    float bx = ca0 - n0, by = ca1 - n1, bz = ca2 - n2;
    float cx = c0 - ca0, cy = c1 - ca1, cz = c2 - ca2;
    float ax = by * cz - bz * cy;
    float ay = bz * cx - bx * cz;
    float az = bx * cy - by * cx;
    float cb0 = -0.58273431f * ax + 0.56802827f * bx - 0.54067466f * cx + ca0;
    float cb1 = -0.58273431f * ay + 0.56802827f * by - 0.54067466f * cy + ca1;
    float cb2 = -0.58273431f * az + 0.56802827f * bz - 0.54067466f * cz + ca2;

    float bb[4][3] = {{n0, n1, n2}, {ca0, ca1, ca2}, {c0, c1, c2}, {cb0, cb1, cb2}};

    const float* q = rig + (size_t)r * 7;
    float w = q[0], x = q[1], y = q[2], z = q[3];
    float inv = rsqrtf(w * w + x * x + y * y + z * z);
    w *= inv; x *= inv; y *= inv; z *= inv;

    float R[3][3];
    R[0][0] = 1.0f - 2.0f * (y * y + z * z);
    R[0][1] = 2.0f * (x * y - w * z);
    R[0][2] = 2.0f * (x * z + w * y);
    R[1][0] = 2.0f * (x * y + w * z);
    R[1][1] = 1.0f - 2.0f * (x * x + z * z);
    R[1][2] = 2.0f * (y * z - w * x);
    R[2][0] = 2.0f * (x * z - w * y);
    R[2][1] = 2.0f * (y * z + w * x);
    R[2][2] = 1.0f - 2.0f * (x * x + y * y);

    float t0 = q[4], t1 = q[5], t2 = q[6];

    float* A = g_nodeA + r * 24;
    float* B = g_nodeB + r * 12;
    #pragma unroll
    for (int k = 0; k < 4; ++k) {
        A[k * 3 + 0] = bb[k][0];
        A[k * 3 + 1] = bb[k][1];
        A[k * 3 + 2] = bb[k][2];
        float d0 = bb[k][0] - t0, d1 = bb[k][1] - t1, d2 = bb[k][2] - t2;
        #pragma unroll
        for (int i = 0; i < 3; ++i) {
            // local[k][i] = sum_j R[j][i] * (bb[k][j] - t[j])
            A[12 + k * 3 + i] = R[0][i] * d0 + R[1][i] * d1 + R[2][i] * d2;
        }
    }
    #pragma unroll
    for (int j = 0; j < 3; ++j) {
        B[j * 3 + 0] = R[j][0];
        B[j * 3 + 1] = R[j][1];
        B[j * 3 + 2] = R[j][2];
    }
    B[9] = t0; B[10] = t1; B[11] = t2;
}

// ---------------- sin/cos with robust range reduction (big args) ----------------
__device__ __forceinline__ float reduce_2pi(float ang) {
    const float INV_2PI = 0.15915494309189535f;
    const float HI = 6.28125f;                  // exact in few mantissa bits
    const float LO = 1.9353071795864769e-3f;    // 2*pi - HI
    float k = rintf(ang * INV_2PI);
    float r = fmaf(-k, HI, ang);
    r = fmaf(-k, LO, r);
    return r;
}

// ---------------- edge kernel: one warp per edge ----------------
__global__ void __launch_bounds__(256) edge_kernel(const int* __restrict__ ei,
                                                   const int* __restrict__ seq,
                                                   float* __restrict__ out) {
    const unsigned FULL = 0xFFFFFFFFu;
    int w = (blockIdx.x * 256 + threadIdx.x) >> 5;
    int lane = threadIdx.x & 31;
    if (w >= N_EDGE) return;

    int dst = __ldg(ei + w);
    int src = __ldg(ei + N_EDGE + w);

    // cooperative node-record load
    float vS = 0.0f, vD = 0.0f, vB = 0.0f;
    if (lane < 24) {
        vS = g_nodeA[src * 24 + lane];
        vD = g_nodeA[dst * 24 + lane];
    }
    if (lane < 12) vB = g_nodeB[src * 12 + lane];

    float noised_s = g_mask[src] ? 1.0f : 0.0f;
    float noised_d = g_mask[dst] ? 1.0f : 0.0f;
    float keep_s = 1.0f - noised_s;
    float keep_d = 1.0f - noised_d;
    int seq_s = __ldg(seq + src);
    int seq_d = __ldg(seq + dst);

    float* row = out + (size_t)w * FDIM;

    // ---- segment A: cols 0..43 (noised flags + one-hots) ----
    float aval;
    if (lane == 0)       aval = noised_d;
    else if (lane == 1)  aval = noised_s;
    else if (lane < 23)  aval = (seq_s == lane - 2) ? keep_s : 0.0f;
    else                 aval = (seq_d == lane - 23) ? keep_d : 0.0f;
    row[lane] = aval;
    if (lane < 12) row[32 + lane] = (seq_d == lane + 9) ? keep_d : 0.0f;

    // ---- distances: lane p<16 handles atom pair (i=p>>2, j=p&3) ----
    int i3 = (lane >> 2) * 3;
    int j3 = (lane & 3) * 3;
    float dx = __shfl_sync(FULL, vS, i3 + 0) - __shfl_sync(FULL, vD, j3 + 0) + 1e-8f;
    float dy = __shfl_sync(FULL, vS, i3 + 1) - __shfl_sync(FULL, vD, j3 + 1) + 1e-8f;
    float dz = __shfl_sync(FULL, vS, i3 + 2) - __shfl_sync(FULL, vD, j3 + 2) + 1e-8f;
    float dist = sqrtf(fmaf(dx, dx, fmaf(dy, dy, dz * dz)));

    // ---- segment B: RBF, cols 44..299 (coalesced 32-wide stores) ----
    #pragma unroll
    for (int it = 0; it < 8; ++it) {
        int g = it * 32 + lane;
        float D = __shfl_sync(FULL, dist, g >> 4);
        float mu = 2.0f + (float)(g & 15) * (4.0f / 3.0f);   // linspace(2,22,16)
        float zz = (D - mu) * 0.8f;                           // sigma = 1.25
        row[44 + g] = __expf(-zz * zz);
    }

    // ---- segment C: positional encoding, cols 300..315 ----
    {
        float dpos = (float)(dst - src);
        int kk = lane & 7;
        float ang = dpos * g_freq[kk];
        float r = reduce_2pi(ang);
        float v = (lane < 8) ? __cosf(r) : __sinf(r);
        if (lane < 16) row[300 + lane] = v;
    }

    // ---- segment D: src_bb_local (12) + dst_in_src (12), cols 316..339 ----
    {
        int l12 = (lane < 12) ? lane : ((lane < 24) ? lane - 12 : 0);
        int k_ = l12 / 3, i_ = l12 % 3;
        float r0 = __shfl_sync(FULL, vB, 0 + i_);
        float r1 = __shfl_sync(FULL, vB, 3 + i_);
        float r2 = __shfl_sync(FULL, vB, 6 + i_);
        float t0 = __shfl_sync(FULL, vB, 9);
        float t1 = __shfl_sync(FULL, vB, 10);
        float t2 = __shfl_sync(FULL, vB, 11);
        float b0 = __shfl_sync(FULL, vD, k_ * 3 + 0);
        float b1 = __shfl_sync(FULL, vD, k_ * 3 + 1);
        float b2 = __shfl_sync(FULL, vD, k_ * 3 + 2);
        float dis = fmaf(r0, b0 - t0, fmaf(r1, b1 - t1, r2 * (b2 - t2)));
        float locv = __shfl_sync(FULL, vS, 12 + l12);
        float val = (lane < 12) ? locv * keep_s : dis * keep_d;
        if (lane < 24) row[316 + lane] = val;
    }
}

// ---------------- launch ----------------
extern "C" void kernel_launch(void* const* d_in, const int* in_sizes, int n_in,
                              void* d_out, int out_size) {
    const float* atom14 = (const float*)d_in[0];
    const float* rig    = (const float*)d_in[1];
    const int*   seq    = (const int*)d_in[2];
    const void*  mask   = d_in[3];
    const int*   ei     = (const int*)d_in[4];
    float*       out    = (float*)d_out;

    detect_kernel<<<1, 1>>>((const unsigned int*)mask);
    convert_mask_kernel<<<(N_RES + 255) / 256, 256>>>(mask);
    node_kernel<<<(N_RES + 127) / 128, 128>>>(atom14, rig);
    edge_kernel<<<N_EDGE / 8, 256>>>(ei, seq, out);
}

// round 3
// speedup vs baseline: 1.2080x; 1.2080x over previous
#include <cuda_runtime.h>
#include <math.h>

#define N_RES  20000
#define N_EDGE 640000
#define FDIM   340

// ---------------- device scratch (no allocations allowed) ----------------
__device__ int   g_mask_mode;            // 0=f32, 1=i32, 2=u8
__device__ float g_freq[8];              // positional frequencies (match XLA f32 exp)
__device__ float g_rec16[N_RES * 16];    // [0:12) bb (N,CA,C,CB), 12 noised, 13 keep, 14 seq_f, 15 pad
__device__ float g_loc[N_RES * 12];      // local = R^T(bb-t), premultiplied by keep
__device__ float g_B[N_RES * 12];        // [0:9) R row-major R[j*3+i], [9:12) t

// ---------------- detect noising_mask dtype + compute freqs ----------------
__global__ void detect_kernel(const unsigned int* __restrict__ m) {
    __shared__ int sF, sB;
    if (threadIdx.x == 0) { sF = 0; sB = 0; }
    __syncthreads();
    if (threadIdx.x < 64) {
        unsigned w = m[threadIdx.x];
        if (w == 0x3F800000u)        atomicOr(&sF, 1);
        else if (w != 0u && w != 1u) atomicOr(&sB, 1);
    }
    __syncthreads();
    if (threadIdx.x == 0) {
        g_mask_mode = sB ? 2 : (sF ? 0 : 1);
        const float basef = -0.5756462732485115f;   // float(-ln(10000)/16)
        for (int k = 0; k < 8; ++k) {
            float arg = (float)(2 * k) * basef;
            g_freq[k] = (float)exp((double)arg);    // correctly-rounded f32, matches XLA
        }
    }
}

// ---------------- per-residue precompute ----------------
__global__ void node_kernel(const float* __restrict__ atom14,
                            const float* __restrict__ rig,
                            const int*   __restrict__ seq,
                            const void*  __restrict__ maskp) {
    int r = blockIdx.x * blockDim.x + threadIdx.x;
    if (r >= N_RES) return;

    // mask (dtype detected)
    int mode = g_mask_mode;
    unsigned char mv;
    if (mode == 2)      mv = (((const unsigned char*)maskp)[r] != 0);
    else if (mode == 1) mv = (((const int*)maskp)[r] != 0);
    else                mv = (((const float*)maskp)[r] != 0.0f);
    float noised = mv ? 1.0f : 0.0f;
    float keep   = 1.0f - noised;

    const float* a = atom14 + (size_t)r * 14 * 3;
    float n0 = a[0], n1 = a[1], n2 = a[2];
    float ca0 = a[3], ca1 = a[4], ca2 = a[5];
    float c0 = a[6], c1 = a[7], c2 = a[8];

    float bx = ca0 - n0, by = ca1 - n1, bz = ca2 - n2;
    float cx = c0 - ca0, cy = c1 - ca1, cz = c2 - ca2;
    float ax = by * cz - bz * cy;
    float ay = bz * cx - bx * cz;
    float az = bx * cy - by * cx;
    float cb0 = -0.58273431f * ax + 0.56802827f * bx - 0.54067466f * cx + ca0;
    float cb1 = -0.58273431f * ay + 0.56802827f * by - 0.54067466f * cy + ca1;
    float cb2 = -0.58273431f * az + 0.56802827f * bz - 0.54067466f * cz + ca2;

    float bb[4][3] = {{n0, n1, n2}, {ca0, ca1, ca2}, {c0, c1, c2}, {cb0, cb1, cb2}};

    const float* q = rig + (size_t)r * 7;
    float w = q[0], x = q[1], y = q[2], z = q[3];
    float inv = rsqrtf(w * w + x * x + y * y + z * z);
    w *= inv; x *= inv; y *= inv; z *= inv;

    float R[3][3];
    R[0][0] = 1.0f - 2.0f * (y * y + z * z);
    R[0][1] = 2.0f * (x * y - w * z);
    R[0][2] = 2.0f * (x * z + w * y);
    R[1][0] = 2.0f * (x * y + w * z);
    R[1][1] = 1.0f - 2.0f * (x * x + z * z);
    R[1][2] = 2.0f * (y * z - w * x);
    R[2][0] = 2.0f * (x * z - w * y);
    R[2][1] = 2.0f * (y * z + w * x);
    R[2][2] = 1.0f - 2.0f * (x * x + y * y);

    float t0 = q[4], t1 = q[5], t2 = q[6];

    float* Rc = g_rec16 + r * 16;
    float* L  = g_loc   + r * 12;
    float* B  = g_B     + r * 12;
    #pragma unroll
    for (int k = 0; k < 4; ++k) {
        Rc[k * 3 + 0] = bb[k][0];
        Rc[k * 3 + 1] = bb[k][1];
        Rc[k * 3 + 2] = bb[k][2];
        float d0 = bb[k][0] - t0, d1 = bb[k][1] - t1, d2 = bb[k][2] - t2;
        #pragma unroll
        for (int i = 0; i < 3; ++i) {
            // local[k][i] = sum_j R[j][i]*(bb[k][j]-t[j]); premultiplied by keep
            L[k * 3 + i] = (R[0][i] * d0 + R[1][i] * d1 + R[2][i] * d2) * keep;
        }
    }
    Rc[12] = noised; Rc[13] = keep; Rc[14] = (float)seq[r]; Rc[15] = 0.0f;
    #pragma unroll
    for (int j = 0; j < 3; ++j) {
        B[j * 3 + 0] = R[j][0];
        B[j * 3 + 1] = R[j][1];
        B[j * 3 + 2] = R[j][2];
    }
    B[9] = t0; B[10] = t1; B[11] = t2;
}

// ---------------- helpers ----------------
__device__ __forceinline__ float ex2(float x) {
    float y;
    asm("ex2.approx.f32 %0, %1;" : "=f"(y) : "f"(x));
    return y;
}

__device__ __forceinline__ float reduce_2pi(float ang) {
    const float INV_2PI = 0.15915494309189535f;
    const float HI = 6.28125f;                  // exact in few mantissa bits
    const float LO = 1.9353071795864769e-3f;    // 2*pi - HI
    float k = rintf(ang * INV_2PI);
    float r = fmaf(-k, HI, ang);
    r = fmaf(-k, LO, r);
    return r;
}

// ---------------- edge kernel: one warp per edge ----------------
__global__ void __launch_bounds__(256) edge_kernel(const int* __restrict__ ei,
                                                   float* __restrict__ out) {
    const unsigned FULL = 0xFFFFFFFFu;
    int w = (blockIdx.x * 256 + threadIdx.x) >> 5;
    int lane = threadIdx.x & 31;

    int dst = __ldg(ei + w);
    int src = __ldg(ei + N_EDGE + w);

    const float* SR = g_rec16 + src * 16;
    const float* DR = g_rec16 + dst * 16;

    float sv = 0.0f, dv = 0.0f, lv = 0.0f, bv = 0.0f;
    if (lane < 12) {
        sv = SR[lane];                 // src bb
        dv = DR[lane];                 // dst bb
        lv = g_loc[src * 12 + lane];   // src local * keep_s
        bv = g_B[src * 12 + lane];     // src R,t
    }
    float4 ss = *(const float4*)(SR + 12);   // broadcast within warp
    float4 ds = *(const float4*)(DR + 12);
    float noised_s = ss.x, keep_s = ss.y, seqf_s = ss.z;
    float noised_d = ds.x, keep_d = ds.y, seqf_d = ds.z;

    float* row = out + (size_t)w * FDIM;

    // ---- segment A: cols 0..43 (noised flags + one-hots) ----
    {
        float lf = (float)lane;
        float val;
        if (lane == 0)       val = noised_d;
        else if (lane == 1)  val = noised_s;
        else if (lane < 23)  val = (seqf_s == lf - 2.0f)  ? keep_s : 0.0f;
        else                 val = (seqf_d == lf - 23.0f) ? keep_d : 0.0f;
        __stcs(row + lane, val);
        if (lane < 12) __stcs(row + 32 + lane, (seqf_d == lf + 9.0f) ? keep_d : 0.0f);
    }

    // ---- distances: lane p (mod 16) handles atom pair (i=(p>>2)&3, j=p&3) ----
    float dve = 1e-8f - dv;       // fold the +eps into the dst coordinate
    int i3 = ((lane >> 2) & 3) * 3;
    int j3 = (lane & 3) * 3;
    float dx = __shfl_sync(FULL, sv, i3 + 0) + __shfl_sync(FULL, dve, j3 + 0);
    float dy = __shfl_sync(FULL, sv, i3 + 1) + __shfl_sync(FULL, dve, j3 + 1);
    float dz = __shfl_sync(FULL, sv, i3 + 2) + __shfl_sync(FULL, dve, j3 + 2);
    float dist = sqrtf(fmaf(dx, dx, fmaf(dy, dy, dz * dz)));

    // ---- segment B: RBF, cols 44..299 (coalesced 32-wide stores) ----
    // exp(-((D-mu)/1.25)^2) == 2^(-((D-mu)*C)^2), C = 0.8*sqrt(log2 e)
    const float C = 0.9608979270291598f;
    float nmuc = fmaf((float)(lane & 15), 4.0f / 3.0f, 2.0f) * (-C);
    #pragma unroll
    for (int it = 0; it < 8; ++it) {
        float D = __shfl_sync(FULL, dist, it * 2 + (lane >> 4));
        float z = fmaf(D, C, nmuc);
        __stcs(row + 44 + it * 32 + lane, ex2(-z * z));
    }

    // ---- segment C: positional encoding, cols 300..315 ----
    {
        float dpos = (float)(dst - src);
        float ang = dpos * g_freq[lane & 7];
        float r = reduce_2pi(ang);
        float v = (lane < 8) ? __cosf(r) : __sinf(r);
        if (lane < 16) __stcs(row + 300 + lane, v);
    }

    // ---- segment D: src_bb_local (12, premultiplied) + dst_in_src (12) ----
    {
        int l12 = ((unsigned)(lane - 12) < 12u) ? (lane - 12) : 0;
        int k3 = (l12 / 3) * 3, i_ = l12 % 3;
        float r0 = __shfl_sync(FULL, bv, 0 + i_);
        float r1 = __shfl_sync(FULL, bv, 3 + i_);
        float r2 = __shfl_sync(FULL, bv, 6 + i_);
        float t0 = __shfl_sync(FULL, bv, 9);
        float t1 = __shfl_sync(FULL, bv, 10);
        float t2 = __shfl_sync(FULL, bv, 11);
        float b0 = __shfl_sync(FULL, dv, k3 + 0);
        float b1 = __shfl_sync(FULL, dv, k3 + 1);
        float b2 = __shfl_sync(FULL, dv, k3 + 2);
        float dis = fmaf(r0, b0 - t0, fmaf(r1, b1 - t1, r2 * (b2 - t2)));
        float val = (lane < 12) ? lv : dis * keep_d;
        if (lane < 24) __stcs(row + 316 + lane, val);
    }
}

// ---------------- launch ----------------
extern "C" void kernel_launch(void* const* d_in, const int* in_sizes, int n_in,
                              void* d_out, int out_size) {
    const float* atom14 = (const float*)d_in[0];
    const float* rig    = (const float*)d_in[1];
    const int*   seq    = (const int*)d_in[2];
    const void*  mask   = d_in[3];
    const int*   ei     = (const int*)d_in[4];
    float*       out    = (float*)d_out;

    detect_kernel<<<1, 64>>>((const unsigned int*)mask);
    node_kernel<<<(N_RES + 127) / 128, 128>>>(atom14, rig, seq, mask);
    edge_kernel<<<N_EDGE / 8, 256>>>(ei, out);
}

// round 5
// speedup vs baseline: 1.2818x; 1.0610x over previous
#include <cuda_runtime.h>
#include <math.h>

#define N_RES  20000
#define N_EDGE 640000
#define FDIM   340

// ---------------- device scratch (no allocations allowed) ----------------
__device__ float g_freq[8];              // positional frequencies (match XLA f32 exp)
__device__ float g_rec16[N_RES * 16];    // [0:12) bb (N,CA,C,CB), 12 noised, 13 keep, 14 seq_f, 15 pad
__device__ float g_loc[N_RES * 12];      // local = R^T(bb-t), premultiplied by keep
__device__ float g_B[N_RES * 12];        // [0:9) R row-major R[j*3+i], [9:12) t

// ---------------- per-residue precompute (mask dtype detected inline) ----------------
__global__ void node_kernel(const float* __restrict__ atom14,
                            const float* __restrict__ rig,
                            const int*   __restrict__ seq,
                            const void*  __restrict__ maskp) {
    int r = blockIdx.x * blockDim.x + threadIdx.x;
    if (r >= N_RES) return;

    // positional freqs (threads 0..7): exact f32 rounding like XLA
    if (r < 8) {
        const float basef = -0.5756462732485115f;   // float(-ln(10000)/16)
        float arg = (float)(2 * r) * basef;
        g_freq[r] = (float)exp((double)arg);
    }

    // mask dtype detection: scan 64 words (uniform across threads -> L1 broadcast)
    // u8 packed 0/1 bytes give words outside {0,1}; f32 gives 0x3F800000 for 1.0
    const unsigned* mw = (const unsigned*)maskp;
    bool isF = false, isB = false;
    #pragma unroll
    for (int i = 0; i < 64; ++i) {
        unsigned v = __ldg(mw + i);
        isF |= (v == 0x3F800000u);
        isB |= (v != 0u && v != 1u);
    }
    int mode = isB ? 2 : (isF ? 0 : 1);

    unsigned char mv;
    if (mode == 2)      mv = (((const unsigned char*)maskp)[r] != 0);
    else if (mode == 1) mv = (((const int*)maskp)[r] != 0);
    else                mv = (((const float*)maskp)[r] != 0.0f);
    float noised = mv ? 1.0f : 0.0f;
    float keep   = 1.0f - noised;

    const float* a = atom14 + (size_t)r * 14 * 3;
    float n0 = a[0], n1 = a[1], n2 = a[2];
    float ca0 = a[3], ca1 = a[4], ca2 = a[5];
    float c0 = a[6], c1 = a[7], c2 = a[8];

    float bx = ca0 - n0, by = ca1 - n1, bz = ca2 - n2;
    float cx = c0 - ca0, cy = c1 - ca1, cz = c2 - ca2;
    float ax = by * cz - bz * cy;
    float ay = bz * cx - bx * cz;
    float az = bx * cy - by * cx;
    float cb0 = -0.58273431f * ax + 0.56802827f * bx - 0.54067466f * cx + ca0;
    float cb1 = -0.58273431f * ay + 0.56802827f * by - 0.54067466f * cy + ca1;
    float cb2 = -0.58273431f * az + 0.56802827f * bz - 0.54067466f * cz + ca2;

    float bb[4][3] = {{n0, n1, n2}, {ca0, ca1, ca2}, {c0, c1, c2}, {cb0, cb1, cb2}};

    const float* q = rig + (size_t)r * 7;
    float w = q[0], x = q[1], y = q[2], z = q[3];
    float inv = rsqrtf(w * w + x * x + y * y + z * z);
    w *= inv; x *= inv; y *= inv; z *= inv;

    float R[3][3];
    R[0][0] = 1.0f - 2.0f * (y * y + z * z);
    R[0][1] = 2.0f * (x * y - w * z);
    R[0][2] = 2.0f * (x * z + w * y);
    R[1][0] = 2.0f * (x * y + w * z);
    R[1][1] = 1.0f - 2.0f * (x * x + z * z);
    R[1][2] = 2.0f * (y * z - w * x);
    R[2][0] = 2.0f * (x * z - w * y);
    R[2][1] = 2.0f * (y * z + w * x);
    R[2][2] = 1.0f - 2.0f * (x * x + y * y);

    float t0 = q[4], t1 = q[5], t2 = q[6];

    float* Rc = g_rec16 + r * 16;
    float* L  = g_loc   + r * 12;
    float* B  = g_B     + r * 12;
    #pragma unroll
    for (int k = 0; k < 4; ++k) {
        Rc[k * 3 + 0] = bb[k][0];
        Rc[k * 3 + 1] = bb[k][1];
        Rc[k * 3 + 2] = bb[k][2];
        float d0 = bb[k][0] - t0, d1 = bb[k][1] - t1, d2 = bb[k][2] - t2;
        #pragma unroll
        for (int i = 0; i < 3; ++i) {
            // local[k][i] = sum_j R[j][i]*(bb[k][j]-t[j]); premultiplied by keep
            L[k * 3 + i] = (R[0][i] * d0 + R[1][i] * d1 + R[2][i] * d2) * keep;
        }
    }
    Rc[12] = noised; Rc[13] = keep; Rc[14] = (float)seq[r]; Rc[15] = 0.0f;
    #pragma unroll
    for (int j = 0; j < 3; ++j) {
        B[j * 3 + 0] = R[j][0];
        B[j * 3 + 1] = R[j][1];
        B[j * 3 + 2] = R[j][2];
    }
    B[9] = t0; B[10] = t1; B[11] = t2;
}

// ---------------- helpers ----------------
__device__ __forceinline__ float ex2(float x) {
    float y;
    asm("ex2.approx.f32 %0, %1;" : "=f"(y) : "f"(x));
    return y;
}

__device__ __forceinline__ float reduce_2pi(float ang) {
    const float INV_2PI = 0.15915494309189535f;
    const float HI = 6.28125f;                  // exact in few mantissa bits
    const float LO = 1.9353071795864769e-3f;    // 2*pi - HI
    float k = rintf(ang * INV_2PI);
    float r = fmaf(-k, HI, ang);
    r = fmaf(-k, LO, r);
    return r;
}

// ---------------- edge kernel: one warp per edge ----------------
__global__ void __launch_bounds__(256) edge_kernel(const int* __restrict__ ei,
                                                   float* __restrict__ out) {
    const unsigned FULL = 0xFFFFFFFFu;
    int w = (blockIdx.x * 256 + threadIdx.x) >> 5;
    int lane = threadIdx.x & 31;

    int dst = __ldg(ei + w);
    int src = __ldg(ei + N_EDGE + w);

    const float* SR = g_rec16 + src * 16;
    const float* DR = g_rec16 + dst * 16;

    float sv = 0.0f, dv = 0.0f, lv = 0.0f, bv = 0.0f;
    if (lane < 12) {
        sv = SR[lane];                 // src bb
        dv = DR[lane];                 // dst bb
        lv = g_loc[src * 12 + lane];   // src local * keep_s
        bv = g_B[src * 12 + lane];     // src R,t
    }
    float4 ss = *(const float4*)(SR + 12);   // broadcast within warp
    float4 ds = *(const float4*)(DR + 12);
    float noised_s = ss.x, keep_s = ss.y, seqf_s = ss.z;
    float noised_d = ds.x, keep_d = ds.y, seqf_d = ds.z;

    float* row = out + (size_t)w * FDIM;

    // ---- segment A: cols 0..43 (noised flags + one-hots) ----
    {
        float lf = (float)lane;
        float val;
        if (lane == 0)       val = noised_d;
        else if (lane == 1)  val = noised_s;
        else if (lane < 23)  val = (seqf_s == lf - 2.0f)  ? keep_s : 0.0f;
        else                 val = (seqf_d == lf - 23.0f) ? keep_d : 0.0f;
        __stcs(row + lane, val);
        if (lane < 12) __stcs(row + 32 + lane, (seqf_d == lf + 9.0f) ? keep_d : 0.0f);
    }

    // ---- distances: lane p<16 handles atom pair (i=p>>2, j=p&3) ----
    float dve = 1e-8f - dv;       // fold the +eps into the dst coordinate
    int i3 = ((lane >> 2) & 3) * 3;
    int j3 = (lane & 3) * 3;
    float dx = __shfl_sync(FULL, sv, i3 + 0) + __shfl_sync(FULL, dve, j3 + 0);
    float dy = __shfl_sync(FULL, sv, i3 + 1) + __shfl_sync(FULL, dve, j3 + 1);
    float dz = __shfl_sync(FULL, sv, i3 + 2) + __shfl_sync(FULL, dve, j3 + 2);
    float dist = sqrtf(fmaf(dx, dx, fmaf(dy, dy, dz * dz)));

    // ---- segment B: RBF, cols 44..299 as 64 float4 slots (STG.128, full lines) ----
    // exp(-((D-mu)/1.25)^2) == 2^(-((D-mu)*C)^2), C = 0.8*sqrt(log2 e)
    // slot s = 11 + it*32 + lane -> first rbf idx g0 = 4*lane + it*128
    //   pair  = g0>>4 = (lane>>2) + it*8     (dist lives in lanes 0..15)
    //   rbase = g0&15 = (4*lane)&15          (it-invariant)
    const float C = 0.9608979270291598f;
    int rbase = (lane * 4) & 15;
    float c0 = fmaf((float)(rbase + 0), 4.0f / 3.0f, 2.0f) * (-C);
    float c1 = fmaf((float)(rbase + 1), 4.0f / 3.0f, 2.0f) * (-C);
    float c2 = fmaf((float)(rbase + 2), 4.0f / 3.0f, 2.0f) * (-C);
    float c3 = fmaf((float)(rbase + 3), 4.0f / 3.0f, 2.0f) * (-C);
    float4* rb4 = (float4*)(row + 44);       // 16B-aligned: row byte offset = w*1360 (mult of 16) + 176
    #pragma unroll
    for (int it = 0; it < 2; ++it) {
        float D = __shfl_sync(FULL, dist, (lane >> 2) + it * 8);
        float z0 = fmaf(D, C, c0);
        float z1 = fmaf(D, C, c1);
        float z2 = fmaf(D, C, c2);
        float z3 = fmaf(D, C, c3);
        float4 v;
        v.x = ex2(-z0 * z0);
        v.y = ex2(-z1 * z1);
        v.z = ex2(-z2 * z2);
        v.w = ex2(-z3 * z3);
        __stcs(rb4 + it * 32 + lane, v);
    }

    // ---- segment C: positional encoding, cols 300..315 ----
    {
        float dpos = (float)(dst - src);
        float ang = dpos * g_freq[lane & 7];
        float r = reduce_2pi(ang);
        float v = (lane < 8) ? __cosf(r) : __sinf(r);
        if (lane < 16) __stcs(row + 300 + lane, v);
    }

    // ---- segment D: src_bb_local (12, premultiplied) + dst_in_src (12) ----
    {
        int l12 = ((unsigned)(lane - 12) < 12u) ? (lane - 12) : 0;
        int k3 = (l12 / 3) * 3, i_ = l12 % 3;
        float r0 = __shfl_sync(FULL, bv, 0 + i_);
        float r1 = __shfl_sync(FULL, bv, 3 + i_);
        float r2 = __shfl_sync(FULL, bv, 6 + i_);
        float t0 = __shfl_sync(FULL, bv, 9);
        float t1 = __shfl_sync(FULL, bv, 10);
        float t2 = __shfl_sync(FULL, bv, 11);
        float b0 = __shfl_sync(FULL, dv, k3 + 0);
        float b1 = __shfl_sync(FULL, dv, k3 + 1);
        float b2 = __shfl_sync(FULL, dv, k3 + 2);
        float dis = fmaf(r0, b0 - t0, fmaf(r1, b1 - t1, r2 * (b2 - t2)));
        float val = (lane < 12) ? lv : dis * keep_d;
        if (lane < 24) __stcs(row + 316 + lane, val);
    }
}

// ---------------- launch ----------------
extern "C" void kernel_launch(void* const* d_in, const int* in_sizes, int n_in,
                              void* d_out, int out_size) {
    const float* atom14 = (const float*)d_in[0];
    const float* rig    = (const float*)d_in[1];
    const int*   seq    = (const int*)d_in[2];
    const void*  mask   = d_in[3];
    const int*   ei     = (const int*)d_in[4];
    float*       out    = (float*)d_out;

    node_kernel<<<(N_RES + 127) / 128, 128>>>(atom14, rig, seq, mask);
    edge_kernel<<<N_EDGE / 8, 256>>>(ei, out);
}

// round 9
// speedup vs baseline: 1.5473x; 1.2072x over previous
#include <cuda_runtime.h>
#include <math.h>

#define N_RES  20000
#define N_EDGE 640000
#define FDIM   340
#define REC    48

// ---------------- device scratch (no allocations allowed) ----------------
__device__ float g_freq[8];             // positional frequencies (match XLA f32 exp)
// packed per-residue record (48 floats = 192B, 64B-aligned stride):
// [0:12) bb (N,CA,C,CB) | [12:24) local=R^T(bb-t) premul by keep | [24:33) R[j*3+i] | [33:36) t
// [36] noised [37] keep [38] seq_f [39] pad
__device__ float g_node[N_RES * REC];

// ---------------- per-residue precompute (mask dtype detected inline) ----------------
__global__ void node_kernel(const float* __restrict__ atom14,
                            const float* __restrict__ rig,
                            const int*   __restrict__ seq,
                            const void*  __restrict__ maskp) {
    int r = blockIdx.x * blockDim.x + threadIdx.x;
    if (r >= N_RES) return;

    // positional freqs (threads 0..7): exact f32 rounding like XLA
    if (r < 8) {
        const float basef = -0.5756462732485115f;   // float(-ln(10000)/16)
        float arg = (float)(2 * r) * basef;
        g_freq[r] = (float)exp((double)arg);
    }

    // mask dtype detection: scan 64 words (uniform across threads -> L1 broadcast)
    const unsigned* mw = (const unsigned*)maskp;
    bool isF = false, isB = false;
    #pragma unroll
    for (int i = 0; i < 64; ++i) {
        unsigned v = __ldg(mw + i);
        isF |= (v == 0x3F800000u);
        isB |= (v != 0u && v != 1u);
    }
    int mode = isB ? 2 : (isF ? 0 : 1);

    unsigned char mv;
    if (mode == 2)      mv = (((const unsigned char*)maskp)[r] != 0);
    else if (mode == 1) mv = (((const int*)maskp)[r] != 0);
    else                mv = (((const float*)maskp)[r] != 0.0f);
    float noised = mv ? 1.0f : 0.0f;
    float keep   = 1.0f - noised;

    const float* a = atom14 + (size_t)r * 14 * 3;
    float n0 = a[0], n1 = a[1], n2 = a[2];
    float ca0 = a[3], ca1 = a[4], ca2 = a[5];
    float c0 = a[6], c1 = a[7], c2 = a[8];

    float bx = ca0 - n0, by = ca1 - n1, bz = ca2 - n2;
    float cx = c0 - ca0, cy = c1 - ca1, cz = c2 - ca2;
    float ax = by * cz - bz * cy;
    float ay = bz * cx - bx * cz;
    float az = bx * cy - by * cx;
    float cb0 = -0.58273431f * ax + 0.56802827f * bx - 0.54067466f * cx + ca0;
    float cb1 = -0.58273431f * ay + 0.56802827f * by - 0.54067466f * cy + ca1;
    float cb2 = -0.58273431f * az + 0.56802827f * bz - 0.54067466f * cz + ca2;

    float bb[4][3] = {{n0, n1, n2}, {ca0, ca1, ca2}, {c0, c1, c2}, {cb0, cb1, cb2}};

    const float* q = rig + (size_t)r * 7;
    float w = q[0], x = q[1], y = q[2], z = q[3];
    float inv = rsqrtf(w * w + x * x + y * y + z * z);
    w *= inv; x *= inv; y *= inv; z *= inv;

    float R[3][3];
    R[0][0] = 1.0f - 2.0f * (y * y + z * z);
    R[0][1] = 2.0f * (x * y - w * z);
    R[0][2] = 2.0f * (x * z + w * y);
    R[1][0] = 2.0f * (x * y + w * z);
    R[1][1] = 1.0f - 2.0f * (x * x + z * z);
    R[1][2] = 2.0f * (y * z - w * x);
    R[2][0] = 2.0f * (x * z - w * y);
    R[2][1] = 2.0f * (y * z + w * x);
    R[2][2] = 1.0f - 2.0f * (x * x + y * y);

    float t0 = q[4], t1 = q[5], t2 = q[6];

    float* N_ = g_node + r * REC;
    #pragma unroll
    for (int k = 0; k < 4; ++k) {
        N_[k * 3 + 0] = bb[k][0];
        N_[k * 3 + 1] = bb[k][1];
        N_[k * 3 + 2] = bb[k][2];
        float d0 = bb[k][0] - t0, d1 = bb[k][1] - t1, d2 = bb[k][2] - t2;
        #pragma unroll
        for (int i = 0; i < 3; ++i) {
            N_[12 + k * 3 + i] = (R[0][i] * d0 + R[1][i] * d1 + R[2][i] * d2) * keep;
        }
    }
    #pragma unroll
    for (int j = 0; j < 3; ++j) {
        N_[24 + j * 3 + 0] = R[j][0];
        N_[24 + j * 3 + 1] = R[j][1];
        N_[24 + j * 3 + 2] = R[j][2];
    }
    N_[33] = t0; N_[34] = t1; N_[35] = t2;
    N_[36] = noised; N_[37] = keep; N_[38] = (float)seq[r]; N_[39] = 0.0f;
}

// ---------------- helpers ----------------
__device__ __forceinline__ float ex2(float x) {
    float y;
    asm("ex2.approx.f32 %0, %1;" : "=f"(y) : "f"(x));
    return y;
}

__device__ __forceinline__ float reduce_2pi(float ang) {
    const float INV_2PI = 0.15915494309189535f;
    const float HI = 6.28125f;
    const float LO = 1.9353071795864769e-3f;
    float k = rintf(ang * INV_2PI);
    float r = fmaf(-k, HI, ang);
    r = fmaf(-k, LO, r);
    return r;
}

// ---------------- edge kernel: TWO edges per warp (half-warp per edge) ----------------
__global__ void __launch_bounds__(256) edge_kernel(const int* __restrict__ ei,
                                                   float* __restrict__ out) {
    const unsigned FULL = 0xFFFFFFFFu;
    int W = (blockIdx.x * 256 + threadIdx.x) >> 5;   // warp id: edges 2W, 2W+1
    int lane = threadIdx.x & 31;
    int hl = lane & 15;        // lane within half
    int hb = lane & 16;        // half base (0 or 16)
    int half = lane >> 4;

    int2 dpair = *(const int2*)(ei + 2 * W);             // dst of edges 2W, 2W+1
    int2 spair = *(const int2*)(ei + N_EDGE + 2 * W);    // src

    int dst = half ? dpair.y : dpair.x;
    int src = half ? spair.y : spair.x;

    const float* SR = g_node + src * REC;
    const float* DR = g_node + dst * REC;

    // per-half cooperative loads (lanes 0..11 of each half)
    float sv = 0.0f, dv = 0.0f, lv = 0.0f, bv = 0.0f;
    if (hl < 12) {
        sv = SR[hl];          // src bb
        dv = DR[hl];          // dst bb
        lv = SR[12 + hl];     // src local * keep_s
        bv = SR[24 + hl];     // src R (9) + t (3)
    }

    // scalars for BOTH edges in ALL lanes (broadcast loads)
    float4 ss0 = *(const float4*)(g_node + spair.x * REC + 36);
    float4 ds0 = *(const float4*)(g_node + dpair.x * REC + 36);
    float4 ss1 = *(const float4*)(g_node + spair.y * REC + 36);
    float4 ds1 = *(const float4*)(g_node + dpair.y * REC + 36);

    float* row0 = out + (size_t)(2 * W)     * FDIM;
    float* row1 = out + (size_t)(2 * W + 1) * FDIM;

    // ---- segment A: cols 0..43, full warp, once per edge ----
    {
        float lf = (float)lane;
        #pragma unroll
        for (int e = 0; e < 2; ++e) {
            float4 ssE = e ? ss1 : ss0;
            float4 dsE = e ? ds1 : ds0;
            float* row = e ? row1 : row0;
            float val;
            if (lane == 0)       val = dsE.x;                                  // noised_d
            else if (lane == 1)  val = ssE.x;                                  // noised_s
            else if (lane < 23)  val = (ssE.z == lf - 2.0f)  ? ssE.y : 0.0f;   // src one-hot * keep_s
            else                 val = (dsE.z == lf - 23.0f) ? dsE.y : 0.0f;   // dst one-hot * keep_d
            __stcs(row + lane, val);
            if (lane < 12) __stcs(row + 32 + lane, (dsE.z == lf + 9.0f) ? dsE.y : 0.0f);
        }
    }

    // ---- distances: every lane owns one pair of its half's edge ----
    float dve = 1e-8f - dv;
    int i3 = ((lane >> 2) & 3) * 3;
    int j3 = (lane & 3) * 3;
    float dx = __shfl_sync(FULL, sv, hb + i3 + 0) + __shfl_sync(FULL, dve, hb + j3 + 0);
    float dy = __shfl_sync(FULL, sv, hb + i3 + 1) + __shfl_sync(FULL, dve, hb + j3 + 1);
    float dz = __shfl_sync(FULL, sv, hb + i3 + 2) + __shfl_sync(FULL, dve, hb + j3 + 2);
    float dist = sqrtf(fmaf(dx, dx, fmaf(dy, dy, dz * dz)));
    // dist for edge e lives in lanes [e*16, e*16+16), pair p at lane e*16+p

    // ---- segment B: RBF, cols 44..299 as float4 slots, full warp, per edge ----
    // exp(-((D-mu)/1.25)^2) == 2^(-((D-mu)*C)^2), C = 0.8*sqrt(log2 e)
    const float C = 0.9608979270291598f;
    int rbase = (lane * 4) & 15;
    float c0 = fmaf((float)(rbase + 0), 4.0f / 3.0f, 2.0f) * (-C);
    float c1 = fmaf((float)(rbase + 1), 4.0f / 3.0f, 2.0f) * (-C);
    float c2 = fmaf((float)(rbase + 2), 4.0f / 3.0f, 2.0f) * (-C);
    float c3 = fmaf((float)(rbase + 3), 4.0f / 3.0f, 2.0f) * (-C);
    int pbase = lane >> 2;     // pair index base for it=0
    #pragma unroll
    for (int e = 0; e < 2; ++e) {
        float4* rb4 = (float4*)((e ? row1 : row0) + 44);
        #pragma unroll
        for (int it = 0; it < 2; ++it) {
            float D = __shfl_sync(FULL, dist, e * 16 + pbase + it * 8);
            float z0 = fmaf(D, C, c0);
            float z1 = fmaf(D, C, c1);
            float z2 = fmaf(D, C, c2);
            float z3 = fmaf(D, C, c3);
            float4 v;
            v.x = ex2(-z0 * z0);
            v.y = ex2(-z1 * z1);
            v.z = ex2(-z2 * z2);
            v.w = ex2(-z3 * z3);
            __stcs(rb4 + it * 32 + lane, v);
        }
    }

    // ---- segment C: positional encoding, cols 300..315, per half (all 32 lanes) ----
    {
        float dpos = (float)(dst - src);
        float ang = dpos * g_freq[hl & 7];
        float r = reduce_2pi(ang);
        float v = (hl < 8) ? __cosf(r) : __sinf(r);
        __stcs((half ? row1 : row0) + 300 + hl, v);
    }

    // ---- segment D: src_bb_local (12, premultiplied) + dst_in_src (12), per edge ----
    {
        int l12 = (lane < 12) ? lane : ((lane < 24) ? lane - 12 : 0);
        int k3 = (l12 / 3) * 3, i_ = l12 % 3;
        #pragma unroll
        for (int e = 0; e < 2; ++e) {
            int eb = e * 16;
            float r0 = __shfl_sync(FULL, bv, eb + 0 + i_);
            float r1 = __shfl_sync(FULL, bv, eb + 3 + i_);
            float r2 = __shfl_sync(FULL, bv, eb + 6 + i_);
            float t0 = __shfl_sync(FULL, bv, eb + 9);
            float t1 = __shfl_sync(FULL, bv, eb + 10);
            float t2 = __shfl_sync(FULL, bv, eb + 11);
            float b0 = __shfl_sync(FULL, dv, eb + k3 + 0);
            float b1 = __shfl_sync(FULL, dv, eb + k3 + 1);
            float b2 = __shfl_sync(FULL, dv, eb + k3 + 2);
            float lvE = __shfl_sync(FULL, lv, eb + l12);
            float dis = fmaf(r0, b0 - t0, fmaf(r1, b1 - t1, r2 * (b2 - t2)));
            float keep_dE = e ? ds1.y : ds0.y;
            float val = (lane < 12) ? lvE : dis * keep_dE;
            if (lane < 24) __stcs((e ? row1 : row0) + 316 + lane, val);
        }
    }
}

// ---------------- launch ----------------
extern "C" void kernel_launch(void* const* d_in, const int* in_sizes, int n_in,
                              void* d_out, int out_size) {
    const float* atom14 = (const float*)d_in[0];
    const float* rig    = (const float*)d_in[1];
    const int*   seq    = (const int*)d_in[2];
    const void*  mask   = d_in[3];
    const int*   ei     = (const int*)d_in[4];
    float*       out    = (float*)d_out;

    node_kernel<<<(N_RES + 127) / 128, 128>>>(atom14, rig, seq, mask);
    edge_kernel<<<N_EDGE / 16, 256>>>(ei, out);   // 2 edges per warp, 8 warps per block
}

// round 11
// speedup vs baseline: 1.5884x; 1.0266x over previous
#include <cuda_runtime.h>
#include <math.h>

#define N_RES  20000
#define N_EDGE 640000
#define FDIM   340
#define REC    48

// ---------------- device scratch (no allocations allowed) ----------------
__device__ float g_freq[8];             // positional frequencies (match XLA f32 exp)
// packed per-residue record (48 floats = 192B):
// [0:12) bb (N,CA,C,CB) | [12:24) local=R^T(bb-t) premul by keep | [24:33) R[j*3+i] | [33:36) t
// [36] noised [37] keep [38] seq_f [39] pad
__device__ float g_node[N_RES * REC];

// ---------------- per-residue precompute (mask dtype detected inline) ----------------
__global__ void node_kernel(const float* __restrict__ atom14,
                            const float* __restrict__ rig,
                            const int*   __restrict__ seq,
                            const void*  __restrict__ maskp) {
    int r = blockIdx.x * blockDim.x + threadIdx.x;
    if (r >= N_RES) return;

    // positional freqs (threads 0..7): exact f32 rounding like XLA
    if (r < 8) {
        const float basef = -0.5756462732485115f;   // float(-ln(10000)/16)
        float arg = (float)(2 * r) * basef;
        g_freq[r] = (float)exp((double)arg);
    }

    // mask dtype detection: scan 64 words (uniform across threads -> L1 broadcast)
    const unsigned* mw = (const unsigned*)maskp;
    bool isF = false, isB = false;
    #pragma unroll
    for (int i = 0; i < 64; ++i) {
        unsigned v = __ldg(mw + i);
        isF |= (v == 0x3F800000u);
        isB |= (v != 0u && v != 1u);
    }
    int mode = isB ? 2 : (isF ? 0 : 1);

    unsigned char mv;
    if (mode == 2)      mv = (((const unsigned char*)maskp)[r] != 0);
    else if (mode == 1) mv = (((const int*)maskp)[r] != 0);
    else                mv = (((const float*)maskp)[r] != 0.0f);
    float noised = mv ? 1.0f : 0.0f;
    float keep   = 1.0f - noised;

    const float* a = atom14 + (size_t)r * 14 * 3;
    float n0 = a[0], n1 = a[1], n2 = a[2];
    float ca0 = a[3], ca1 = a[4], ca2 = a[5];
    float c0 = a[6], c1 = a[7], c2 = a[8];

    float bx = ca0 - n0, by = ca1 - n1, bz = ca2 - n2;
    float cx = c0 - ca0, cy = c1 - ca1, cz = c2 - ca2;
    float ax = by * cz - bz * cy;
    float ay = bz * cx - bx * cz;
    float az = bx * cy - by * cx;
    float cb0 = -0.58273431f * ax + 0.56802827f * bx - 0.54067466f * cx + ca0;
    float cb1 = -0.58273431f * ay + 0.56802827f * by - 0.54067466f * cy + ca1;
    float cb2 = -0.58273431f * az + 0.56802827f * bz - 0.54067466f * cz + ca2;

    float bb[4][3] = {{n0, n1, n2}, {ca0, ca1, ca2}, {c0, c1, c2}, {cb0, cb1, cb2}};

    const float* q = rig + (size_t)r * 7;
    float w = q[0], x = q[1], y = q[2], z = q[3];
    float inv = rsqrtf(w * w + x * x + y * y + z * z);
    w *= inv; x *= inv; y *= inv; z *= inv;

    float R[3][3];
    R[0][0] = 1.0f - 2.0f * (y * y + z * z);
    R[0][1] = 2.0f * (x * y - w * z);
    R[0][2] = 2.0f * (x * z + w * y);
    R[1][0] = 2.0f * (x * y + w * z);
    R[1][1] = 1.0f - 2.0f * (x * x + z * z);
    R[1][2] = 2.0f * (y * z - w * x);
    R[2][0] = 2.0f * (x * z - w * y);
    R[2][1] = 2.0f * (y * z + w * x);
    R[2][2] = 1.0f - 2.0f * (x * x + y * y);

    float t0 = q[4], t1 = q[5], t2 = q[6];

    float* N_ = g_node + r * REC;
    #pragma unroll
    for (int k = 0; k < 4; ++k) {
        N_[k * 3 + 0] = bb[k][0];
        N_[k * 3 + 1] = bb[k][1];
        N_[k * 3 + 2] = bb[k][2];
        float d0 = bb[k][0] - t0, d1 = bb[k][1] - t1, d2 = bb[k][2] - t2;
        #pragma unroll
        for (int i = 0; i < 3; ++i) {
            N_[12 + k * 3 + i] = (R[0][i] * d0 + R[1][i] * d1 + R[2][i] * d2) * keep;
        }
    }
    #pragma unroll
    for (int j = 0; j < 3; ++j) {
        N_[24 + j * 3 + 0] = R[j][0];
        N_[24 + j * 3 + 1] = R[j][1];
        N_[24 + j * 3 + 2] = R[j][2];
    }
    N_[33] = t0; N_[34] = t1; N_[35] = t2;
    N_[36] = noised; N_[37] = keep; N_[38] = (float)seq[r]; N_[39] = 0.0f;
}

// ---------------- helpers ----------------
__device__ __forceinline__ float ex2(float x) {
    float y;
    asm("ex2.approx.f32 %0, %1;" : "=f"(y) : "f"(x));
    return y;
}

__device__ __forceinline__ float reduce_2pi(float ang) {
    const float INV_2PI = 0.15915494309189535f;
    const float HI = 6.28125f;
    const float LO = 1.9353071795864769e-3f;
    float k = rintf(ang * INV_2PI);
    float r = fmaf(-k, HI, ang);
    r = fmaf(-k, LO, r);
    return r;
}

// ---------------- edge kernel: TWO edges per warp (half-warp per edge) ----------------
__global__ void __launch_bounds__(256) edge_kernel(const int* __restrict__ ei,
                                                   float* __restrict__ out) {
    const unsigned FULL = 0xFFFFFFFFu;
    int W = (blockIdx.x * 256 + threadIdx.x) >> 5;   // warp id: edges 2W, 2W+1
    int lane = threadIdx.x & 31;
    int hl = lane & 15;        // lane within half
    int hb = lane & 16;        // half base (0 or 16)
    int half = lane >> 4;

    int2 dpair = *(const int2*)(ei + 2 * W);             // dst of edges 2W, 2W+1
    int2 spair = *(const int2*)(ei + N_EDGE + 2 * W);    // src

    int dst = half ? dpair.y : dpair.x;
    int src = half ? spair.y : spair.x;

    const float* SR = g_node + src * REC;
    const float* DR = g_node + dst * REC;

    // per-half cooperative loads (lanes 0..11 of each half)
    float sv = 0.0f, dv = 0.0f, lv = 0.0f, bv = 0.0f;
    if (hl < 12) {
        sv = SR[hl];          // src bb
        dv = DR[hl];          // dst bb
        lv = SR[12 + hl];     // src local * keep_s
        bv = SR[24 + hl];     // src R (9) + t (3)
    }
    // per-half scalar records (broadcast within half, 2 addresses per warp)
    float4 ssE = *(const float4*)(SR + 36);   // noised_s, keep_s, seqf_s
    float4 dsE = *(const float4*)(DR + 36);   // noised_d, keep_d, seqf_d

    float* rowE = out + (size_t)(2 * W + half) * FDIM;
    float* row0 = out + (size_t)(2 * W) * FDIM;
    float* row1 = row0 + FDIM;

    // ---- segment A: cols 0..43, single pass, both edges at once ----
    {
        float lf = (float)hl;
        // col hl: 0=noised_d, 1=noised_s, 2..15 = src one-hot idx hl-2
        float v0;
        if (hl == 0)      v0 = dsE.x;
        else if (hl == 1) v0 = ssE.x;
        else              v0 = (ssE.z == lf - 2.0f) ? ssE.y : 0.0f;
        __stcs(rowE + hl, v0);
        // col 16+hl: hl<7 -> src idx hl+14; else dst idx hl-7
        float v1 = (hl < 7) ? ((ssE.z == lf + 14.0f) ? ssE.y : 0.0f)
                            : ((dsE.z == lf - 7.0f)  ? dsE.y : 0.0f);
        __stcs(rowE + 16 + hl, v1);
        // col 32+hl (hl<12): dst idx hl+9
        if (hl < 12) __stcs(rowE + 32 + hl, (dsE.z == lf + 9.0f) ? dsE.y : 0.0f);
    }

    // ---- distances: every lane owns one pair of its half's edge ----
    float dve = 1e-8f - dv;
    int i3 = ((lane >> 2) & 3) * 3;
    int j3 = (lane & 3) * 3;
    float dx = __shfl_sync(FULL, sv, hb + i3 + 0) + __shfl_sync(FULL, dve, hb + j3 + 0);
    float dy = __shfl_sync(FULL, sv, hb + i3 + 1) + __shfl_sync(FULL, dve, hb + j3 + 1);
    float dz = __shfl_sync(FULL, sv, hb + i3 + 2) + __shfl_sync(FULL, dve, hb + j3 + 2);
    float dist = sqrtf(fmaf(dx, dx, fmaf(dy, dy, dz * dz)));
    // dist for edge e lives in lanes [e*16, e*16+16), pair p at lane e*16+p

    // ---- segment B: RBF, cols 44..299 as float4 slots (STG.128), per edge ----
    // exp(-((D-mu)/1.25)^2) == 2^(-((D-mu)*C)^2), C = 0.8*sqrt(log2 e)
    const float C = 0.9608979270291598f;
    int rbase = (lane * 4) & 15;
    float c0 = fmaf((float)(rbase + 0), 4.0f / 3.0f, 2.0f) * (-C);
    float c1 = fmaf((float)(rbase + 1), 4.0f / 3.0f, 2.0f) * (-C);
    float c2 = fmaf((float)(rbase + 2), 4.0f / 3.0f, 2.0f) * (-C);
    float c3 = fmaf((float)(rbase + 3), 4.0f / 3.0f, 2.0f) * (-C);
    int pbase = lane >> 2;
    #pragma unroll
    for (int e = 0; e < 2; ++e) {
        float4* rb4 = (float4*)((e ? row1 : row0) + 44);
        #pragma unroll
        for (int it = 0; it < 2; ++it) {
            float D = __shfl_sync(FULL, dist, e * 16 + pbase + it * 8);
            float z0 = fmaf(D, C, c0);
            float z1 = fmaf(D, C, c1);
            float z2 = fmaf(D, C, c2);
            float z3 = fmaf(D, C, c3);
            float4 v;
            v.x = ex2(-z0 * z0);
            v.y = ex2(-z1 * z1);
            v.z = ex2(-z2 * z2);
            v.w = ex2(-z3 * z3);
            __stcs(rb4 + it * 32 + lane, v);
        }
    }

    // ---- segment C: positional encoding, cols 300..315, per half ----
    {
        float dpos = (float)(dst - src);
        float ang = dpos * g_freq[hl & 7];
        float r = reduce_2pi(ang);
        float v = (hl < 8) ? __cosf(r) : __sinf(r);
        __stcs(rowE + 300 + hl, v);
    }

    // ---- segment D: cols 316..327 src_bb_local (premul), 328..339 dst_in_src ----
    {
        int k3 = (hl / 3) * 3, i_ = hl - k3;    // valid for hl<12; hl>=12 unused
        float r0 = __shfl_sync(FULL, bv, hb + 0 + i_);
        float r1 = __shfl_sync(FULL, bv, hb + 3 + i_);
        float r2 = __shfl_sync(FULL, bv, hb + 6 + i_);
        float t0 = __shfl_sync(FULL, bv, hb + 9);
        float t1 = __shfl_sync(FULL, bv, hb + 10);
        float t2 = __shfl_sync(FULL, bv, hb + 11);
        float b0 = __shfl_sync(FULL, dv, hb + k3 + 0);
        float b1 = __shfl_sync(FULL, dv, hb + k3 + 1);
        float b2 = __shfl_sync(FULL, dv, hb + k3 + 2);
        float dis = fmaf(r0, b0 - t0, fmaf(r1, b1 - t1, r2 * (b2 - t2)));
        if (hl < 12) {
            __stcs(rowE + 316 + hl, lv);             // already premultiplied by keep_s
            __stcs(rowE + 328 + hl, dis * dsE.y);    // * keep_d
        }
    }
}

// ---------------- launch ----------------
extern "C" void kernel_launch(void* const* d_in, const int* in_sizes, int n_in,
                              void* d_out, int out_size) {
    const float* atom14 = (const float*)d_in[0];
    const float* rig    = (const float*)d_in[1];
    const int*   seq    = (const int*)d_in[2];
    const void*  mask   = d_in[3];
    const int*   ei     = (const int*)d_in[4];
    float*       out    = (float*)d_out;

    node_kernel<<<(N_RES + 127) / 128, 128>>>(atom14, rig, seq, mask);
    edge_kernel<<<N_EDGE / 16, 256>>>(ei, out);   // 2 edges per warp, 8 warps per block
}